// round 13
// baseline (speedup 1.0000x reference)
#include <cuda_runtime.h>
#include <cuda_fp16.h>
#include <cstdint>

// ---------------- problem constants ----------------
#define N_NODES 100000
#define N_EDGES 1600000
#define C_IN    500
#define C       40        // n_classes
#define H       64        // hidden
#define ALPHA   0.1f
#define K_HOPS  10
#define NBLK    391       // ceil(N_NODES/256)
#define BINS    64
#define CSR_CAP (N_EDGES + 3 * N_NODES)   // padded CSR capacity (1.9M, %4==0)

// ---------------- static scratch (no allocations allowed) ----------------
__device__ __half g_h0h[N_NODES * C];            // h0 (plain) fp16, 80B rows
// hs buffers: N_NODES+1 rows of 128B; row N_NODES is the SENTINEL ZERO ROW
__device__ __align__(128) uint4 g_bufA[(N_NODES + 1) * 8];
__device__ __align__(128) uint4 g_bufB[(N_NODES + 1) * 8];
// [0..N) deg_out, [N..2N) deg_in, [2N..2N+64) bin counts, [2N+64..2N+128) bin cursors
__device__ int     g_deg[2 * N_NODES + 2 * BINS];
__device__ float2  g_inv2[N_NODES];              // {inv_in, inv_out}
__device__ int     g_off[N_NODES + 1];           // PADDED offsets (%4==0)
__device__ int     g_cursor[N_NODES];
__device__ int     g_csr_src[CSR_CAP];           // src only; pad slots = N_NODES
__device__ int     g_perm[N_NODES];              // degree-sorted node order
__device__ int     g_part[512];
__device__ int     g_base[512];
// software grid barrier state (zero-init; count self-resets each barrier)
__device__ unsigned int g_bar_count;
__device__ unsigned int g_bar_gen;

// ============================================================
// 1) scores = x @ Wb + bb   [N, 40]  (R9-proven 2-row f32x2 version)
// ============================================================
#define GB_T 128
#define WKT  100
#define KG   (WKT / 4)

__global__ __launch_bounds__(GB_T, 3) void gemm_kernel(
    const float* __restrict__ x, const float* __restrict__ Wb,
    const float* __restrict__ bb, float* __restrict__ scores)
{
    __shared__ __align__(16) float Wt[WKT * C];
    __shared__ float bs[C];

    const int tid = threadIdx.x;
    if (tid < C) bs[tid] = bb[tid];

    const int r0 = blockIdx.x * 256 + tid;
    const int r1 = r0 + 128;
    const size_t r1c = (r1 < N_NODES) ? (size_t)r1 : (size_t)(N_NODES - 1);
    const float4* xa_p = (const float4*)(x + (size_t)r0 * C_IN);
    const float4* xb_p = (const float4*)(x + r1c * C_IN);

    unsigned long long acc0[C / 2], acc1[C / 2];
#pragma unroll
    for (int j = 0; j < C / 2; j++) { acc0[j] = 0ull; acc1[j] = 0ull; }

#pragma unroll 1
    for (int t = 0; t < C_IN / WKT; t++) {
        __syncthreads();
        const float4* wsrc = (const float4*)(Wb + t * WKT * C);
        for (int i = tid; i < WKT * C / 4; i += GB_T)
            ((float4*)Wt)[i] = wsrc[i];
        __syncthreads();

        float4 xa = __ldg(xa_p + t * KG);
        float4 xb = __ldg(xb_p + t * KG);
#pragma unroll 1
        for (int kg = 0; kg < KG; kg++) {
            const int nidx = (kg + 1 < KG) ? kg + 1 : kg;
            const float4 na = __ldg(xa_p + t * KG + nidx);
            const float4 nb = __ldg(xb_p + t * KG + nidx);
#pragma unroll
            for (int j = 0; j < 4; j++) {
                const float fa = j == 0 ? xa.x : j == 1 ? xa.y : j == 2 ? xa.z : xa.w;
                const float fb = j == 0 ? xb.x : j == 1 ? xb.y : j == 2 ? xb.z : xb.w;
                unsigned long long xa2, xb2;
                asm("mov.b64 %0, {%1, %1};" : "=l"(xa2) : "f"(fa));
                asm("mov.b64 %0, {%1, %1};" : "=l"(xb2) : "f"(fb));
                const ulonglong2* wr = (const ulonglong2*)(Wt + (kg * 4 + j) * C);
#pragma unroll
                for (int p = 0; p < C / 4; p++) {
                    const ulonglong2 w = wr[p];
                    asm("fma.rn.f32x2 %0, %1, %2, %0;" : "+l"(acc0[2*p  ]) : "l"(w.x), "l"(xa2));
                    asm("fma.rn.f32x2 %0, %1, %2, %0;" : "+l"(acc0[2*p+1]) : "l"(w.y), "l"(xa2));
                    asm("fma.rn.f32x2 %0, %1, %2, %0;" : "+l"(acc1[2*p  ]) : "l"(w.x), "l"(xb2));
                    asm("fma.rn.f32x2 %0, %1, %2, %0;" : "+l"(acc1[2*p+1]) : "l"(w.y), "l"(xb2));
                }
            }
            xa = na; xb = nb;
        }
    }

    float o0[C], o1[C];
#pragma unroll
    for (int j = 0; j < C / 2; j++) {
        float lo, hi;
        asm("mov.b64 {%0, %1}, %2;" : "=f"(lo), "=f"(hi) : "l"(acc0[j]));
        o0[2*j] = lo + bs[2*j]; o0[2*j+1] = hi + bs[2*j+1];
        asm("mov.b64 {%0, %1}, %2;" : "=f"(lo), "=f"(hi) : "l"(acc1[j]));
        o1[2*j] = lo + bs[2*j]; o1[2*j+1] = hi + bs[2*j+1];
    }
    float4* d0 = (float4*)(scores + (size_t)r0 * C);
#pragma unroll
    for (int c4 = 0; c4 < C / 4; c4++)
        d0[c4] = make_float4(o0[c4*4], o0[c4*4+1], o0[c4*4+2], o0[c4*4+3]);
    if (r1 < N_NODES) {
        float4* d1 = (float4*)(scores + (size_t)r1 * C);
#pragma unroll
        for (int c4 = 0; c4 < C / 4; c4++)
            d1[c4] = make_float4(o1[c4*4], o1[c4*4+1], o1[c4*4+2], o1[c4*4+3]);
    }
}

// ============================================================
// 2) MLP -> h0 (fp16) + hs0 = inv_out*h0 (padded rows, bufA)
// ============================================================
#define MLP_BS 128
__global__ __launch_bounds__(MLP_BS) void mlp_kernel(
    const float* __restrict__ scores,
    const float* __restrict__ W1, const float* __restrict__ b1,
    const float* __restrict__ W2, const float* __restrict__ b2)
{
    __shared__ float W1s[C * H];
    __shared__ float W2s[H * C];
    __shared__ float b1s[H];
    __shared__ float b2s[C];
    __shared__ float p_sh[C * MLP_BS];

    const int tid = threadIdx.x;
    for (int i = tid; i < C * H; i += MLP_BS) W1s[i] = W1[i];
    for (int i = tid; i < H * C; i += MLP_BS) W2s[i] = W2[i];
    if (tid < H) b1s[tid] = b1[tid];
    if (tid < C) b2s[tid] = b2[tid];
    __syncthreads();

    const int node = blockIdx.x * MLP_BS + tid;
    if (node >= N_NODES) return;

    const float4* sc4 = (const float4*)(scores + (size_t)node * C);
    float m = -1e30f;
#pragma unroll
    for (int q = 0; q < C / 4; q++) {
        const float4 v = sc4[q];
        p_sh[(q * 4 + 0) * MLP_BS + tid] = v.x;
        p_sh[(q * 4 + 1) * MLP_BS + tid] = v.y;
        p_sh[(q * 4 + 2) * MLP_BS + tid] = v.z;
        p_sh[(q * 4 + 3) * MLP_BS + tid] = v.w;
        m = fmaxf(m, fmaxf(fmaxf(v.x, v.y), fmaxf(v.z, v.w)));
    }
    float s = 0.f;
    for (int i = 0; i < C; i++) {
        const float e = __expf(p_sh[i * MLP_BS + tid] - m);
        p_sh[i * MLP_BS + tid] = e;
        s += e;
    }
    const float inv = 1.f / s;

    float h1[H];
#pragma unroll
    for (int j = 0; j < H; j++) h1[j] = b1s[j];
    for (int i = 0; i < C; i++) {
        const float pv = p_sh[i * MLP_BS + tid] * inv;
#pragma unroll
        for (int j = 0; j < H; j++) h1[j] += pv * W1s[i * H + j];
    }
#pragma unroll
    for (int j = 0; j < H; j++) h1[j] = fmaxf(h1[j], 0.f);

    float o[C];
    for (int c = 0; c < C; c++) {
        float a = b2s[c];
#pragma unroll
        for (int j = 0; j < H; j++) a += h1[j] * W2s[j * C + c];
        o[c] = a;
    }

    const float2 iv = __ldg(&g_inv2[node]);
    uint4 pk_h[5], pk_s[5];
    uint32_t* ph = (uint32_t*)pk_h;
    uint32_t* ps = (uint32_t*)pk_s;
#pragma unroll
    for (int p = 0; p < C / 2; p++) {
        const __half2 hv = __floats2half2_rn(o[2*p], o[2*p+1]);
        ph[p] = *(const uint32_t*)&hv;
        const __half2 sv = __floats2half2_rn(o[2*p] * iv.y, o[2*p+1] * iv.y);
        ps[p] = *(const uint32_t*)&sv;
    }
    uint4* hr = (uint4*)(g_h0h + (size_t)node * C);
#pragma unroll
    for (int p = 0; p < 5; p++) hr[p] = pk_h[p];
    uint4* sr = g_bufA + (size_t)node * 8;
#pragma unroll
    for (int p = 0; p < 5; p++) sr[p] = pk_s[p];
}

// ============================================================
// 3) degrees (4 edges/thread, int4)
// ============================================================
__global__ void deg_kernel(const int4* __restrict__ src4, const int4* __restrict__ dst4)
{
    const int i = blockIdx.x * blockDim.x + threadIdx.x;
    if (i < N_EDGES / 4) {
        const int4 s = __ldg(src4 + i);
        const int4 d = __ldg(dst4 + i);
        atomicAdd(&g_deg[s.x], 1); atomicAdd(&g_deg[s.y], 1);
        atomicAdd(&g_deg[s.z], 1); atomicAdd(&g_deg[s.w], 1);
        atomicAdd(&g_deg[N_NODES + d.x], 1); atomicAdd(&g_deg[N_NODES + d.y], 1);
        atomicAdd(&g_deg[N_NODES + d.z], 1); atomicAdd(&g_deg[N_NODES + d.w], 1);
    }
}

// ============================================================
// 4) inv-sqrt -> packed float2 {inv_in, inv_out}  (REAL degrees)
// ============================================================
__global__ void invsqrt_kernel()
{
    const int i = blockIdx.x * blockDim.x + threadIdx.x;
    if (i < N_NODES) {
        const int d_o = g_deg[i];
        const int d_i = g_deg[N_NODES + i];
        g_inv2[i] = make_float2(d_i > 0 ? rsqrtf((float)d_i) : 0.f,
                                d_o > 0 ? rsqrtf((float)d_o) : 0.f);
    }
}

// padded degree: round deg_in up to multiple of 4
__device__ __forceinline__ int pdeg_of(int node)
{
    return (g_deg[N_NODES + node] + 3) & ~3;
}

// ============================================================
// 5) 3-phase parallel exclusive scan of PADDED deg -> g_off, g_cursor
// ============================================================
__global__ __launch_bounds__(256) void scan1_kernel()
{
    __shared__ int red[256];
    const int node = blockIdx.x * 256 + threadIdx.x;
    const int v = (node < N_NODES) ? pdeg_of(node) : 0;
    red[threadIdx.x] = v;
    __syncthreads();
#pragma unroll
    for (int o = 128; o > 0; o >>= 1) {
        if (threadIdx.x < o) red[threadIdx.x] += red[threadIdx.x + o];
        __syncthreads();
    }
    if (threadIdx.x == 0) g_part[blockIdx.x] = red[0];
}

__global__ __launch_bounds__(512) void scan2_kernel()
{
    __shared__ int sm[512];
    const int t = threadIdx.x;
    const int v = (t < NBLK) ? g_part[t] : 0;
    sm[t] = v;
    __syncthreads();
#pragma unroll
    for (int o = 1; o < 512; o <<= 1) {
        const int u = (t >= o) ? sm[t - o] : 0;
        __syncthreads();
        sm[t] += u;
        __syncthreads();
    }
    if (t < NBLK) g_base[t] = sm[t] - v;
    if (t == 511) g_off[N_NODES] = sm[511];
}

__global__ __launch_bounds__(256) void scan3_kernel()
{
    __shared__ int sm[256];
    const int node = blockIdx.x * 256 + threadIdx.x;
    const int v = (node < N_NODES) ? pdeg_of(node) : 0;
    sm[threadIdx.x] = v;
    __syncthreads();
#pragma unroll
    for (int o = 1; o < 256; o <<= 1) {
        const int u = (threadIdx.x >= o) ? sm[threadIdx.x - o] : 0;
        __syncthreads();
        sm[threadIdx.x] += u;
        __syncthreads();
    }
    if (node < N_NODES) {
        const int off = g_base[blockIdx.x] + sm[threadIdx.x] - v;
        g_off[node] = off;
        g_cursor[node] = off;
    }
}

// ============================================================
// 6) counting sort of nodes by deg_in (64 bins) -> g_perm
// ============================================================
__global__ void hist_kernel()
{
    const int i = blockIdx.x * blockDim.x + threadIdx.x;
    if (i < N_NODES) {
        const int d = min(g_deg[N_NODES + i], BINS - 1);
        atomicAdd(&g_deg[2 * N_NODES + d], 1);
    }
}

__global__ __launch_bounds__(BINS) void binscan_kernel()
{
    __shared__ int sm[BINS];
    const int t = threadIdx.x;
    const int v = g_deg[2 * N_NODES + t];
    sm[t] = v;
    __syncthreads();
#pragma unroll
    for (int o = 1; o < BINS; o <<= 1) {
        const int u = (t >= o) ? sm[t - o] : 0;
        __syncthreads();
        sm[t] += u;
        __syncthreads();
    }
    g_deg[2 * N_NODES + BINS + t] = sm[t] - v;
}

__global__ void scatter_kernel()
{
    const int i = blockIdx.x * blockDim.x + threadIdx.x;
    if (i < N_NODES) {
        const int d = min(g_deg[N_NODES + i], BINS - 1);
        const int pos = atomicAdd(&g_deg[2 * N_NODES + BINS + d], 1);
        g_perm[pos] = i;
    }
}

// ============================================================
// 7) sentinel fill + CSR fill
// ============================================================
__global__ void sentinel_kernel()
{
    const int i = blockIdx.x * blockDim.x + threadIdx.x;
    if (i < CSR_CAP / 4)
        ((int4*)g_csr_src)[i] = make_int4(N_NODES, N_NODES, N_NODES, N_NODES);
}

__global__ void fill_csr_kernel(const int4* __restrict__ src4, const int4* __restrict__ dst4)
{
    const int i = blockIdx.x * blockDim.x + threadIdx.x;
    if (i < N_EDGES / 4) {
        const int4 s = __ldg(src4 + i);
        const int4 d = __ldg(dst4 + i);
        g_csr_src[atomicAdd(&g_cursor[d.x], 1)] = s.x;
        g_csr_src[atomicAdd(&g_cursor[d.y], 1)] = s.y;
        g_csr_src[atomicAdd(&g_cursor[d.z], 1)] = s.z;
        g_csr_src[atomicAdd(&g_cursor[d.w], 1)] = s.w;
    }
}

// ============================================================
// 8) PERSISTENT hop kernel: all K_HOPS in one launch.
//    Software grid barrier between hops (all blocks co-resident:
//    grid sized by occupancy API on the host).
//    L1-coherence: hs gathers/stores use .cg (L2-only) because L1
//    is NOT coherent across SMs within a launch. Immutable data
//    (csr/perm/off/inv2/h0) stays on the __ldg L1 path.
// ============================================================
#define HOP_BS 256
#define NPW 6
#define NPB ((HOP_BS / 32) * NPW)            // 48 nodes per block-chunk

__device__ __forceinline__ void grid_barrier(int nblocks)
{
    __syncthreads();
    if (threadIdx.x == 0) {
        __threadfence();                                   // release my stores
        const unsigned int gen = *(volatile unsigned int*)&g_bar_gen;
        const unsigned int ticket = atomicAdd(&g_bar_count, 1u);
        if (ticket == (unsigned int)nblocks - 1u) {
            g_bar_count = 0u;                              // reset before release
            __threadfence();
            atomicAdd(&g_bar_gen, 1u);                     // release everyone
        } else {
            while (*(volatile unsigned int*)&g_bar_gen == gen) { }
        }
        __threadfence();                                   // acquire
    }
    __syncthreads();
}

__global__ __launch_bounds__(HOP_BS) void hops_persist_kernel(
    float* __restrict__ out_f, int nblocks)
{
    const int warp = threadIdx.x >> 5;
    const int lane = threadIdx.x & 31;
    const int sub = lane / 5;                // 0..5 active; lanes 30,31 idle
    const int q = lane - sub * 5;            // uint4 index within 128B row
    const bool lane_ok = (sub < NPW);
    const int nchunks = (N_NODES + NPB - 1) / NPB;

#pragma unroll 1
    for (int k = 0; k < K_HOPS; k++) {
        const uint4* hs_in = (k & 1) ? g_bufB : g_bufA;
        uint4* hs_out      = (k & 1) ? g_bufA : g_bufB;
        const bool last = (k == K_HOPS - 1);

#pragma unroll 1
        for (int chunk = blockIdx.x; chunk < nchunks; chunk += nblocks) {
            const int idx = chunk * NPB + warp * NPW + sub;
            if (lane_ok && idx < N_NODES) {
                const int node = __ldg(&g_perm[idx]);
                const int beg4 = __ldg(&g_off[node]) >> 2;
                const int end4 = __ldg(&g_off[node + 1]) >> 2;

                float acc[8];
#pragma unroll
                for (int i = 0; i < 8; i++) acc[i] = 0.f;

                const int4* csr4 = (const int4*)g_csr_src;
#pragma unroll 2
                for (int e4 = beg4; e4 < end4; e4++) {
                    const int4 s4 = __ldg(csr4 + e4);
#pragma unroll
                    for (int g = 0; g < 4; g++) {
                        const int s = g == 0 ? s4.x : g == 1 ? s4.y : g == 2 ? s4.z : s4.w;
                        const uint4 hv = __ldcg(hs_in + (size_t)s * 8 + q);
                        const __half2* hp = (const __half2*)&hv;
#pragma unroll
                        for (int i = 0; i < 4; i++) {
                            const float2 f = __half22float2(hp[i]);
                            acc[2 * i + 0] += f.x;
                            acc[2 * i + 1] += f.y;
                        }
                    }
                }

                const float2 iv = __ldg(&g_inv2[node]);
                const float w = (1.f - ALPHA) * iv.x;

                const uint4 h0v = __ldg((const uint4*)g_h0h + (size_t)node * 5 + q);
                const __half2* h0p = (const __half2*)&h0v;
                float o[8];
#pragma unroll
                for (int i = 0; i < 4; i++) {
                    const float2 f = __half22float2(h0p[i]);
                    o[2 * i + 0] = w * acc[2 * i + 0] + ALPHA * f.x;
                    o[2 * i + 1] = w * acc[2 * i + 1] + ALPHA * f.y;
                }

                if (last) {
                    float4* dst = (float4*)(out_f + (size_t)node * C + q * 8);
                    dst[0] = make_float4(o[0], o[1], o[2], o[3]);
                    dst[1] = make_float4(o[4], o[5], o[6], o[7]);
                } else {
                    uint4 pk;
                    uint32_t* pw = (uint32_t*)&pk;
#pragma unroll
                    for (int i = 0; i < 4; i++) {
                        const __half2 hv2 = __floats2half2_rn(o[2 * i] * iv.y,
                                                              o[2 * i + 1] * iv.y);
                        pw[i] = *(const uint32_t*)&hv2;
                    }
                    __stcg(&hs_out[(size_t)node * 8 + q], pk);
                }
            }
        }
        if (k < K_HOPS - 1) grid_barrier(nblocks);
    }
}

// ============================================================
// launch — prep forked to a second stream (overlapped with
// gemm+mlp); all 10 hops fused into one persistent kernel.
// ============================================================
extern "C" void kernel_launch(void* const* d_in, const int* in_sizes, int n_in,
                              void* d_out, int out_size)
{
    const float* x  = (const float*)d_in[0];
    const int*   ei = (const int*)d_in[1];
    const float* Wb = (const float*)d_in[2];
    const float* bb = (const float*)d_in[3];
    const float* W1 = (const float*)d_in[4];
    const float* b1 = (const float*)d_in[5];
    const float* W2 = (const float*)d_in[6];
    const float* b2 = (const float*)d_in[7];

    float* out = (float*)d_out;
    float* adjust = out;                              // [N, 40]
    float* scores = out + (size_t)N_NODES * C;        // [N, 40]

    const int4* src4 = (const int4*)ei;
    const int4* dst4 = (const int4*)(ei + N_EDGES);

    int *degp;
    cudaGetSymbolAddress((void**)&degp, g_deg);

    cudaStream_t s2;
    cudaStreamCreateWithFlags(&s2, cudaStreamNonBlocking);
    cudaEvent_t e_fork, e_inv, e_csr;
    cudaEventCreateWithFlags(&e_fork, cudaEventDisableTiming);
    cudaEventCreateWithFlags(&e_inv, cudaEventDisableTiming);
    cudaEventCreateWithFlags(&e_csr, cudaEventDisableTiming);

    const int e4blk = (N_EDGES / 4 + 255) / 256;
    const int nblk  = (N_NODES + 255) / 256;

    // main stream: memset, then fork
    cudaMemsetAsync(degp, 0, (2 * N_NODES + 2 * BINS) * sizeof(int), 0);
    cudaEventRecord(e_fork, 0);
    cudaStreamWaitEvent(s2, e_fork, 0);

    // prep chain on s2
    deg_kernel<<<e4blk, 256, 0, s2>>>(src4, dst4);
    invsqrt_kernel<<<nblk, 256, 0, s2>>>();
    cudaEventRecord(e_inv, s2);                       // inv2 ready (mlp needs it)
    scan1_kernel<<<NBLK, 256, 0, s2>>>();
    scan2_kernel<<<1, 512, 0, s2>>>();
    scan3_kernel<<<NBLK, 256, 0, s2>>>();
    hist_kernel<<<nblk, 256, 0, s2>>>();
    binscan_kernel<<<1, BINS, 0, s2>>>();
    scatter_kernel<<<nblk, 256, 0, s2>>>();
    sentinel_kernel<<<(CSR_CAP / 4 + 255) / 256, 256, 0, s2>>>();
    fill_csr_kernel<<<e4blk, 256, 0, s2>>>(src4, dst4);
    cudaEventRecord(e_csr, s2);                       // CSR + perm ready

    // main stream: gemm runs concurrently with prep
    gemm_kernel<<<(N_NODES + 255) / 256, GB_T>>>(x, Wb, bb, scores);
    cudaStreamWaitEvent(0, e_inv, 0);                 // mlp needs inv2
    mlp_kernel<<<(N_NODES + MLP_BS - 1) / MLP_BS, MLP_BS>>>(scores, W1, b1, W2, b2);
    cudaStreamWaitEvent(0, e_csr, 0);                 // hops need CSR (join)

    // persistent fused hops: grid sized so ALL blocks are co-resident
    int bpm = 0;
    cudaOccupancyMaxActiveBlocksPerMultiprocessor(&bpm, hops_persist_kernel,
                                                  HOP_BS, 0);
    if (bpm < 1) bpm = 1;
    int sms = 0;
    cudaDeviceGetAttribute(&sms, cudaDevAttrMultiProcessorCount, 0);
    if (sms < 1) sms = 148;
    int nblocks = bpm * sms;
    const int nchunks = (N_NODES + NPB - 1) / NPB;
    if (nblocks > nchunks) nblocks = nchunks;

    hops_persist_kernel<<<nblocks, HOP_BS>>>(adjust, nblocks);
}

// round 14
// speedup vs baseline: 1.1149x; 1.1149x over previous
#include <cuda_runtime.h>
#include <cuda_fp16.h>
#include <cstdint>

// ---------------- problem constants ----------------
#define N_NODES 100000
#define N_EDGES 1600000
#define C_IN    500
#define C       40        // n_classes
#define H       64        // hidden
#define ALPHA   0.1f
#define K_HOPS  10
#define NBLK    391       // ceil(N_NODES/256)
#define BINS    64
#define CSR_CAP (N_EDGES + 3 * N_NODES)   // padded CSR capacity (1.9M, %4==0)

// ---------------- static scratch (no allocations allowed) ----------------
__device__ __half g_h0h[N_NODES * C];            // h0 (plain) fp16, 80B rows
// hs buffers: N_NODES+1 rows of 128B; row N_NODES is the SENTINEL ZERO ROW
__device__ __align__(128) uint4 g_bufA[(N_NODES + 1) * 8];
__device__ __align__(128) uint4 g_bufB[(N_NODES + 1) * 8];
// [0..N) deg_out, [N..2N) deg_in, [2N..2N+64) bin counts, [2N+64..2N+128) bin cursors
__device__ int     g_deg[2 * N_NODES + 2 * BINS];
__device__ float2  g_inv2[N_NODES];              // {inv_in, inv_out}
__device__ int     g_off[N_NODES + 1];           // PADDED offsets (%4==0)
__device__ int     g_cursor[N_NODES];
__device__ int     g_csr_src[CSR_CAP];           // src only; pad slots = N_NODES
__device__ int     g_perm[N_NODES];              // degree-sorted node order
__device__ int     g_part[512];
__device__ int     g_base[512];

// ============================================================
// 1) FUSED: scores = x@Wb+bb, then softmax+MLP epilogue -> h0 (fp16).
//    Mainloop: 2 rows/thread, fma.rn.f32x2, W K-tiles in smem.
//    Epilogue: Wt region is dead -> aliased as p_sh; W1/W2 loaded
//    into smem; exact mlp math per thread for its 2 rows.
//    Dynamic smem = max(mainloop, epilogue) = 41.4KB -> 3 CTAs/SM.
// ============================================================
#define GB_T 128
#define WKT  100
#define KG   (WKT / 4)
// epilogue smem layout (floats): p_sh[C*GB_T] | W1s[C*H] | W2s[H*C] | b1s[H] | b2s[C]
#define EP_PSH   0
#define EP_W1    (C * GB_T)
#define EP_W2    (EP_W1 + C * H)
#define EP_B1    (EP_W2 + H * C)
#define EP_B2    (EP_B1 + H)
#define EP_TOTAL (EP_B2 + C)
#define GEMM_SMEM_FLOATS ((EP_TOTAL > WKT * C) ? EP_TOTAL : (WKT * C))
#define GEMM_SMEM (GEMM_SMEM_FLOATS * 4)

__global__ __launch_bounds__(GB_T, 3) void gemm_mlp_kernel(
    const float* __restrict__ x, const float* __restrict__ Wb,
    const float* __restrict__ bb, float* __restrict__ scores,
    const float* __restrict__ W1, const float* __restrict__ b1,
    const float* __restrict__ W2, const float* __restrict__ b2)
{
    extern __shared__ __align__(16) float sm[];
    float* Wt = sm;                                 // mainloop view
    __shared__ float bs[C];

    const int tid = threadIdx.x;
    if (tid < C) bs[tid] = bb[tid];

    const int r0 = blockIdx.x * 256 + tid;          // always < N (grid=391)
    const int r1 = r0 + 128;
    const size_t r1c = (r1 < N_NODES) ? (size_t)r1 : (size_t)(N_NODES - 1);
    const float4* xa_p = (const float4*)(x + (size_t)r0 * C_IN);
    const float4* xb_p = (const float4*)(x + r1c * C_IN);

    unsigned long long acc0[C / 2], acc1[C / 2];
#pragma unroll
    for (int j = 0; j < C / 2; j++) { acc0[j] = 0ull; acc1[j] = 0ull; }

#pragma unroll 1
    for (int t = 0; t < C_IN / WKT; t++) {          // 5 tiles of K=100
        __syncthreads();
        const float4* wsrc = (const float4*)(Wb + t * WKT * C);
        for (int i = tid; i < WKT * C / 4; i += GB_T)
            ((float4*)Wt)[i] = wsrc[i];
        __syncthreads();

        float4 xa = __ldg(xa_p + t * KG);
        float4 xb = __ldg(xb_p + t * KG);
#pragma unroll 1
        for (int kg = 0; kg < KG; kg++) {
            const int nidx = (kg + 1 < KG) ? kg + 1 : kg;
            const float4 na = __ldg(xa_p + t * KG + nidx);
            const float4 nb = __ldg(xb_p + t * KG + nidx);
#pragma unroll
            for (int j = 0; j < 4; j++) {
                const float fa = j == 0 ? xa.x : j == 1 ? xa.y : j == 2 ? xa.z : xa.w;
                const float fb = j == 0 ? xb.x : j == 1 ? xb.y : j == 2 ? xb.z : xb.w;
                unsigned long long xa2, xb2;
                asm("mov.b64 %0, {%1, %1};" : "=l"(xa2) : "f"(fa));
                asm("mov.b64 %0, {%1, %1};" : "=l"(xb2) : "f"(fb));
                const ulonglong2* wr = (const ulonglong2*)(Wt + (kg * 4 + j) * C);
#pragma unroll
                for (int p = 0; p < C / 4; p++) {
                    const ulonglong2 w = wr[p];
                    asm("fma.rn.f32x2 %0, %1, %2, %0;" : "+l"(acc0[2*p  ]) : "l"(w.x), "l"(xa2));
                    asm("fma.rn.f32x2 %0, %1, %2, %0;" : "+l"(acc0[2*p+1]) : "l"(w.y), "l"(xa2));
                    asm("fma.rn.f32x2 %0, %1, %2, %0;" : "+l"(acc1[2*p  ]) : "l"(w.x), "l"(xb2));
                    asm("fma.rn.f32x2 %0, %1, %2, %0;" : "+l"(acc1[2*p+1]) : "l"(w.y), "l"(xb2));
                }
            }
            xa = na; xb = nb;
        }
    }

    // unpack accumulators + bias
    float o0[C], o1[C];
#pragma unroll
    for (int j = 0; j < C / 2; j++) {
        float lo, hi;
        asm("mov.b64 {%0, %1}, %2;" : "=f"(lo), "=f"(hi) : "l"(acc0[j]));
        o0[2*j] = lo + bs[2*j]; o0[2*j+1] = hi + bs[2*j+1];
        asm("mov.b64 {%0, %1}, %2;" : "=f"(lo), "=f"(hi) : "l"(acc1[j]));
        o1[2*j] = lo + bs[2*j]; o1[2*j+1] = hi + bs[2*j+1];
    }

    // write scores (direct output)
    float4* d0 = (float4*)(scores + (size_t)r0 * C);
#pragma unroll
    for (int c4 = 0; c4 < C / 4; c4++)
        d0[c4] = make_float4(o0[c4*4], o0[c4*4+1], o0[c4*4+2], o0[c4*4+3]);
    if (r1 < N_NODES) {
        float4* d1 = (float4*)(scores + (size_t)r1 * C);
#pragma unroll
        for (int c4 = 0; c4 < C / 4; c4++)
            d1[c4] = make_float4(o1[c4*4], o1[c4*4+1], o1[c4*4+2], o1[c4*4+3]);
    }

    // ---- epilogue: re-partition smem (Wt is dead) ----
    __syncthreads();
    float* p_sh = sm + EP_PSH;
    float* W1s  = sm + EP_W1;
    float* W2s  = sm + EP_W2;
    float* b1s  = sm + EP_B1;
    float* b2s  = sm + EP_B2;
    for (int i = tid; i < C * H; i += GB_T) W1s[i] = W1[i];
    for (int i = tid; i < H * C; i += GB_T) W2s[i] = W2[i];
    if (tid < H) b1s[tid] = b1[tid];
    if (tid < C) b2s[tid] = b2[tid];
    __syncthreads();

    // each thread processes its own 2 rows sequentially (own p_sh column)
#pragma unroll 1
    for (int rr = 0; rr < 2; rr++) {
        const int row = (rr == 0) ? r0 : r1;
        if (row >= N_NODES) continue;
        const float* o = (rr == 0) ? o0 : o1;

        float m = -1e30f;
#pragma unroll
        for (int c = 0; c < C; c++) m = fmaxf(m, o[c]);
        float s = 0.f;
        for (int i = 0; i < C; i++) {
            const float e = __expf(o[i] - m);
            p_sh[i * GB_T + tid] = e;
            s += e;
        }
        const float inv = 1.f / s;

        float h1[H];
#pragma unroll
        for (int j = 0; j < H; j++) h1[j] = b1s[j];
        for (int i = 0; i < C; i++) {
            const float pv = p_sh[i * GB_T + tid] * inv;
#pragma unroll
            for (int j = 0; j < H; j++) h1[j] += pv * W1s[i * H + j];
        }
#pragma unroll
        for (int j = 0; j < H; j++) h1[j] = fmaxf(h1[j], 0.f);

        float oo[C];
        for (int c = 0; c < C; c++) {
            float a = b2s[c];
#pragma unroll
            for (int j = 0; j < H; j++) a += h1[j] * W2s[j * C + c];
            oo[c] = a;
        }

        uint4 pk[5];
        uint32_t* pw = (uint32_t*)pk;
#pragma unroll
        for (int p = 0; p < C / 2; p++) {
            const __half2 hv = __floats2half2_rn(oo[2*p], oo[2*p+1]);
            pw[p] = *(const uint32_t*)&hv;
        }
        uint4* hr = (uint4*)(g_h0h + (size_t)row * C);
#pragma unroll
        for (int p = 0; p < 5; p++) hr[p] = pk[p];
    }
}

// ============================================================
// 2) hs0 = inv_out * h0  (into padded bufA rows) — tiny, after e_inv
// ============================================================
__global__ void hs0_scale_kernel()
{
    const int node = blockIdx.x * blockDim.x + threadIdx.x;
    if (node >= N_NODES) return;
    const float iv = __ldg(&g_inv2[node]).y;         // inv_out
    const uint4* hr = (const uint4*)(g_h0h + (size_t)node * C);
    uint4* sr = g_bufA + (size_t)node * 8;
#pragma unroll
    for (int p = 0; p < 5; p++) {
        const uint4 hv = __ldg(hr + p);
        const __half2* hp = (const __half2*)&hv;
        uint4 pk;
        uint32_t* pw = (uint32_t*)&pk;
#pragma unroll
        for (int i = 0; i < 4; i++) {
            const float2 f = __half22float2(hp[i]);
            const __half2 sv = __floats2half2_rn(f.x * iv, f.y * iv);
            pw[i] = *(const uint32_t*)&sv;
        }
        sr[p] = pk;
    }
}

// ============================================================
// 3) degrees (4 edges/thread, int4)
// ============================================================
__global__ void deg_kernel(const int4* __restrict__ src4, const int4* __restrict__ dst4)
{
    const int i = blockIdx.x * blockDim.x + threadIdx.x;
    if (i < N_EDGES / 4) {
        const int4 s = __ldg(src4 + i);
        const int4 d = __ldg(dst4 + i);
        atomicAdd(&g_deg[s.x], 1); atomicAdd(&g_deg[s.y], 1);
        atomicAdd(&g_deg[s.z], 1); atomicAdd(&g_deg[s.w], 1);
        atomicAdd(&g_deg[N_NODES + d.x], 1); atomicAdd(&g_deg[N_NODES + d.y], 1);
        atomicAdd(&g_deg[N_NODES + d.z], 1); atomicAdd(&g_deg[N_NODES + d.w], 1);
    }
}

// ============================================================
// 4) inv-sqrt -> packed float2 {inv_in, inv_out}
// ============================================================
__global__ void invsqrt_kernel()
{
    const int i = blockIdx.x * blockDim.x + threadIdx.x;
    if (i < N_NODES) {
        const int d_o = g_deg[i];
        const int d_i = g_deg[N_NODES + i];
        g_inv2[i] = make_float2(d_i > 0 ? rsqrtf((float)d_i) : 0.f,
                                d_o > 0 ? rsqrtf((float)d_o) : 0.f);
    }
}

__device__ __forceinline__ int pdeg_of(int node)
{
    return (g_deg[N_NODES + node] + 3) & ~3;
}

// ============================================================
// 5) 3-phase parallel exclusive scan of PADDED deg -> g_off, g_cursor
// ============================================================
__global__ __launch_bounds__(256) void scan1_kernel()
{
    __shared__ int red[256];
    const int node = blockIdx.x * 256 + threadIdx.x;
    const int v = (node < N_NODES) ? pdeg_of(node) : 0;
    red[threadIdx.x] = v;
    __syncthreads();
#pragma unroll
    for (int o = 128; o > 0; o >>= 1) {
        if (threadIdx.x < o) red[threadIdx.x] += red[threadIdx.x + o];
        __syncthreads();
    }
    if (threadIdx.x == 0) g_part[blockIdx.x] = red[0];
}

__global__ __launch_bounds__(512) void scan2_kernel()
{
    __shared__ int sm[512];
    const int t = threadIdx.x;
    const int v = (t < NBLK) ? g_part[t] : 0;
    sm[t] = v;
    __syncthreads();
#pragma unroll
    for (int o = 1; o < 512; o <<= 1) {
        const int u = (t >= o) ? sm[t - o] : 0;
        __syncthreads();
        sm[t] += u;
        __syncthreads();
    }
    if (t < NBLK) g_base[t] = sm[t] - v;
    if (t == 511) g_off[N_NODES] = sm[511];
}

__global__ __launch_bounds__(256) void scan3_kernel()
{
    __shared__ int sm[256];
    const int node = blockIdx.x * 256 + threadIdx.x;
    const int v = (node < N_NODES) ? pdeg_of(node) : 0;
    sm[threadIdx.x] = v;
    __syncthreads();
#pragma unroll
    for (int o = 1; o < 256; o <<= 1) {
        const int u = (threadIdx.x >= o) ? sm[threadIdx.x - o] : 0;
        __syncthreads();
        sm[threadIdx.x] += u;
        __syncthreads();
    }
    if (node < N_NODES) {
        const int off = g_base[blockIdx.x] + sm[threadIdx.x] - v;
        g_off[node] = off;
        g_cursor[node] = off;
    }
}

// ============================================================
// 6) counting sort of nodes by deg_in (64 bins) -> g_perm
// ============================================================
__global__ void hist_kernel()
{
    const int i = blockIdx.x * blockDim.x + threadIdx.x;
    if (i < N_NODES) {
        const int d = min(g_deg[N_NODES + i], BINS - 1);
        atomicAdd(&g_deg[2 * N_NODES + d], 1);
    }
}

__global__ __launch_bounds__(BINS) void binscan_kernel()
{
    __shared__ int sm[BINS];
    const int t = threadIdx.x;
    const int v = g_deg[2 * N_NODES + t];
    sm[t] = v;
    __syncthreads();
#pragma unroll
    for (int o = 1; o < BINS; o <<= 1) {
        const int u = (t >= o) ? sm[t - o] : 0;
        __syncthreads();
        sm[t] += u;
        __syncthreads();
    }
    g_deg[2 * N_NODES + BINS + t] = sm[t] - v;
}

__global__ void scatter_kernel()
{
    const int i = blockIdx.x * blockDim.x + threadIdx.x;
    if (i < N_NODES) {
        const int d = min(g_deg[N_NODES + i], BINS - 1);
        const int pos = atomicAdd(&g_deg[2 * N_NODES + BINS + d], 1);
        g_perm[pos] = i;
    }
}

// ============================================================
// 7) sentinel fill + CSR fill
// ============================================================
__global__ void sentinel_kernel()
{
    const int i = blockIdx.x * blockDim.x + threadIdx.x;
    if (i < CSR_CAP / 4)
        ((int4*)g_csr_src)[i] = make_int4(N_NODES, N_NODES, N_NODES, N_NODES);
}

__global__ void fill_csr_kernel(const int4* __restrict__ src4, const int4* __restrict__ dst4)
{
    const int i = blockIdx.x * blockDim.x + threadIdx.x;
    if (i < N_EDGES / 4) {
        const int4 s = __ldg(src4 + i);
        const int4 d = __ldg(dst4 + i);
        g_csr_src[atomicAdd(&g_cursor[d.x], 1)] = s.x;
        g_csr_src[atomicAdd(&g_cursor[d.y], 1)] = s.y;
        g_csr_src[atomicAdd(&g_cursor[d.z], 1)] = s.z;
        g_csr_src[atomicAdd(&g_cursor[d.w], 1)] = s.w;
    }
}

// ============================================================
// 8) one APPNP hop (R12-proven): 6 nodes/warp, 5 lanes/node,
//    uint4/lane, int4 src reads (padded CSR), sentinel adds 0.
// ============================================================
#define HOP_BS 256
#define NPW 6
#define NPB ((HOP_BS / 32) * NPW)            // 48 nodes per block

template <bool LAST>
__global__ __launch_bounds__(HOP_BS) void hop_kernel(
    const uint4* __restrict__ hs_in,
    uint4* __restrict__ hs_out, float* __restrict__ out_f)
{
    const int warp = threadIdx.x >> 5;
    const int lane = threadIdx.x & 31;
    const int sub = lane / 5;
    const int q = lane - sub * 5;
    if (sub >= NPW) return;

    const int idx = (blockIdx.x * (HOP_BS / 32) + warp) * NPW + sub;
    if (idx >= N_NODES) return;
    const int node = __ldg(&g_perm[idx]);

    const int beg4 = __ldg(&g_off[node]) >> 2;
    const int end4 = __ldg(&g_off[node + 1]) >> 2;

    float acc[8];
#pragma unroll
    for (int i = 0; i < 8; i++) acc[i] = 0.f;

    const int4* csr4 = (const int4*)g_csr_src;
#pragma unroll 2
    for (int e4 = beg4; e4 < end4; e4++) {
        const int4 s4 = __ldg(csr4 + e4);
#pragma unroll
        for (int g = 0; g < 4; g++) {
            const int s = g == 0 ? s4.x : g == 1 ? s4.y : g == 2 ? s4.z : s4.w;
            const uint4 hv = __ldg(hs_in + (size_t)s * 8 + q);
            const __half2* hp = (const __half2*)&hv;
#pragma unroll
            for (int i = 0; i < 4; i++) {
                const float2 f = __half22float2(hp[i]);
                acc[2 * i + 0] += f.x;
                acc[2 * i + 1] += f.y;
            }
        }
    }

    const float2 iv = __ldg(&g_inv2[node]);
    const float w = (1.f - ALPHA) * iv.x;

    const uint4 h0v = __ldg((const uint4*)g_h0h + (size_t)node * 5 + q);
    const __half2* h0p = (const __half2*)&h0v;
    float o[8];
#pragma unroll
    for (int i = 0; i < 4; i++) {
        const float2 f = __half22float2(h0p[i]);
        o[2 * i + 0] = w * acc[2 * i + 0] + ALPHA * f.x;
        o[2 * i + 1] = w * acc[2 * i + 1] + ALPHA * f.y;
    }

    if (LAST) {
        float4* dst = (float4*)(out_f + (size_t)node * C + q * 8);
        dst[0] = make_float4(o[0], o[1], o[2], o[3]);
        dst[1] = make_float4(o[4], o[5], o[6], o[7]);
    } else {
        uint4 pk;
        uint32_t* pw = (uint32_t*)&pk;
#pragma unroll
        for (int i = 0; i < 4; i++) {
            const __half2 hv = __floats2half2_rn(o[2 * i] * iv.y, o[2 * i + 1] * iv.y);
            pw[i] = *(const uint32_t*)&hv;
        }
        hs_out[(size_t)node * 8 + q] = pk;
    }
}

// ============================================================
// launch — prep on stream 2 overlapped with fused gemm+mlp;
// hs0 scaling after e_inv; per-hop launches (R12-proven).
// ============================================================
extern "C" void kernel_launch(void* const* d_in, const int* in_sizes, int n_in,
                              void* d_out, int out_size)
{
    const float* x  = (const float*)d_in[0];
    const int*   ei = (const int*)d_in[1];
    const float* Wb = (const float*)d_in[2];
    const float* bb = (const float*)d_in[3];
    const float* W1 = (const float*)d_in[4];
    const float* b1 = (const float*)d_in[5];
    const float* W2 = (const float*)d_in[6];
    const float* b2 = (const float*)d_in[7];

    float* out = (float*)d_out;
    float* adjust = out;                              // [N, 40]
    float* scores = out + (size_t)N_NODES * C;        // [N, 40]

    const int4* src4 = (const int4*)ei;
    const int4* dst4 = (const int4*)(ei + N_EDGES);

    uint4 *Ap, *Bp;
    int *degp;
    cudaGetSymbolAddress((void**)&Ap, g_bufA);
    cudaGetSymbolAddress((void**)&Bp, g_bufB);
    cudaGetSymbolAddress((void**)&degp, g_deg);

    cudaStream_t s2;
    cudaStreamCreateWithFlags(&s2, cudaStreamNonBlocking);
    cudaEvent_t e_fork, e_inv, e_csr;
    cudaEventCreateWithFlags(&e_fork, cudaEventDisableTiming);
    cudaEventCreateWithFlags(&e_inv, cudaEventDisableTiming);
    cudaEventCreateWithFlags(&e_csr, cudaEventDisableTiming);

    const int e4blk = (N_EDGES / 4 + 255) / 256;
    const int nblk  = (N_NODES + 255) / 256;

    // main stream: memset, then fork
    cudaMemsetAsync(degp, 0, (2 * N_NODES + 2 * BINS) * sizeof(int), 0);
    cudaEventRecord(e_fork, 0);
    cudaStreamWaitEvent(s2, e_fork, 0);

    // prep chain on s2
    deg_kernel<<<e4blk, 256, 0, s2>>>(src4, dst4);
    invsqrt_kernel<<<nblk, 256, 0, s2>>>();
    cudaEventRecord(e_inv, s2);                       // inv2 ready
    scan1_kernel<<<NBLK, 256, 0, s2>>>();
    scan2_kernel<<<1, 512, 0, s2>>>();
    scan3_kernel<<<NBLK, 256, 0, s2>>>();
    hist_kernel<<<nblk, 256, 0, s2>>>();
    binscan_kernel<<<1, BINS, 0, s2>>>();
    scatter_kernel<<<nblk, 256, 0, s2>>>();
    sentinel_kernel<<<(CSR_CAP / 4 + 255) / 256, 256, 0, s2>>>();
    fill_csr_kernel<<<e4blk, 256, 0, s2>>>(src4, dst4);
    cudaEventRecord(e_csr, s2);                       // CSR + perm ready

    // main stream: fused gemm+mlp (independent of prep)
    gemm_mlp_kernel<<<(N_NODES + 255) / 256, GB_T, GEMM_SMEM>>>(
        x, Wb, bb, scores, W1, b1, W2, b2);
    cudaStreamWaitEvent(0, e_inv, 0);                 // hs0 needs inv2
    hs0_scale_kernel<<<nblk, 256>>>();
    cudaStreamWaitEvent(0, e_csr, 0);                 // hops need CSR

    const int hop_grid = (N_NODES + NPB - 1) / NPB;
    const uint4* hin = Ap;                            // hs0 in bufA
    for (int k = 0; k < K_HOPS; k++) {
        if (k == K_HOPS - 1) {
            hop_kernel<true><<<hop_grid, HOP_BS>>>(hin, nullptr, adjust);
        } else {
            uint4* o = (k % 2 == 0) ? Bp : Ap;
            hop_kernel<false><<<hop_grid, HOP_BS>>>(hin, o, nullptr);
            hin = o;
        }
    }
}